// round 13
// baseline (speedup 1.0000x reference)
#include <cuda_runtime.h>
#include <cuda_bf16.h>
#include <cstdint>

#define N_TOT 8192
#define BSZ   4096
#define D     256
#define TILE  128
#define EPS_  1e-7f
// dot of 8x-scaled fp8 vectors = 64*S; exp(S/T) = exp2(D * log2(e)/(0.07*64))
#define K2E8  0.32203014305557203f

// smem: A strip 32KB | B0 32KB | B1 32KB | label ring 4 x 512B
#define OFF_B0     32768
#define OFF_B1     65536
#define OFF_LRING  98304
#define SMEM_TOTAL 100352

__device__ uint8_t g_F8[N_TOT * D];   // e4m3, features pre-scaled by 8
__device__ float g_pos[N_TOT];
__device__ float g_tot[N_TOT];

// ---------------------------------------------------------------------------
// helpers
// ---------------------------------------------------------------------------
__device__ __forceinline__ uint32_t smem_u32(const void* p) {
    uint32_t a;
    asm("{ .reg .u64 t; cvta.to.shared.u64 t, %1; cvt.u32.u64 %0, t; }" : "=r"(a) : "l"(p));
    return a;
}
__device__ __forceinline__ void cp16(uint32_t s, const void* g) {
    asm volatile("cp.async.cg.shared.global [%0], [%1], 16;" :: "r"(s), "l"(g) : "memory");
}
__device__ __forceinline__ void cp_commit() {
    asm volatile("cp.async.commit_group;" ::: "memory");
}
template <int N> __device__ __forceinline__ void cp_wait() {
    asm volatile("cp.async.wait_group %0;" :: "n"(N) : "memory");
}
__device__ __forceinline__ void ldsm4(uint32_t* r, uint32_t addr) {
    asm volatile("ldmatrix.sync.aligned.m8n8.x4.shared.b16 {%0,%1,%2,%3}, [%4];"
                 : "=r"(r[0]), "=r"(r[1]), "=r"(r[2]), "=r"(r[3]) : "r"(addr));
}
__device__ __forceinline__ void ldsm2(uint32_t* r, uint32_t addr) {
    asm volatile("ldmatrix.sync.aligned.m8n8.x2.shared.b16 {%0,%1}, [%2];"
                 : "=r"(r[0]), "=r"(r[1]) : "r"(addr));
}
// FP8 e4m3 MMA: m16n8k32, fp32 accum (sm_89+ instruction, legal at sm_103 base)
__device__ __forceinline__ void mma_e4m3(float* c, const uint32_t* a, const uint32_t* b) {
    asm volatile(
        "mma.sync.aligned.m16n8k32.row.col.f32.e4m3.e4m3.f32 "
        "{%0,%1,%2,%3}, {%4,%5,%6,%7}, {%8,%9}, {%0,%1,%2,%3};"
        : "+f"(c[0]), "+f"(c[1]), "+f"(c[2]), "+f"(c[3])
        : "r"(a[0]), "r"(a[1]), "r"(a[2]), "r"(a[3]), "r"(b[0]), "r"(b[1]));
}
__device__ __forceinline__ float fexp2(float x) {
    float y;
    asm("ex2.approx.f32 %0, %1;" : "=f"(y) : "f"(x));
    return y;
}
// pack two fp32 -> e4m3x2 (lo byte = second operand)
__device__ __forceinline__ uint16_t cvt2_e4m3(float hi, float lo) {
    uint16_t v;
    asm("cvt.rn.satfinite.e4m3x2.f32 %0, %1, %2;" : "=h"(v) : "f"(hi), "f"(lo));
    return v;
}

// stage 128x256B fp8 tile; XOR swizzle: 16B chunk c (0..15) of row r -> c^(r&7)
__device__ __forceinline__ void cp_tile(uint32_t dst, const uint8_t* src, int tid) {
    #pragma unroll
    for (int it = 0; it < 8; it++) {
        int idx = it * 256 + tid;            // 0..2047 chunks
        int r = idx >> 4, c = idx & 15;
        uint32_t d = dst + r * 256 + ((c ^ (r & 7)) << 4);
        cp16(d, src + idx * 16);
    }
}

// ---------------------------------------------------------------------------
// Kernel 1: repack fp32 [bsz,2,d] -> e4m3 contrast rows [n,d] (x8); zero accums
// ---------------------------------------------------------------------------
__global__ void prep_kernel(const float* __restrict__ feats) {
    int idx = blockIdx.x * 256 + threadIdx.x;   // 0..131071, one 16B out chunk
    int i = idx >> 4;                           // row 0..8191
    int c = idx & 15;
    int v = i >> 12;
    int b = i & (BSZ - 1);
    const float4* src = (const float4*)(feats + (size_t)(b * 2 + v) * D + c * 16);
    uint32_t w[4];
    #pragma unroll
    for (int q = 0; q < 4; q++) {
        float4 f = src[q];
        uint16_t lo = cvt2_e4m3(f.y * 8.f, f.x * 8.f);
        uint16_t hi = cvt2_e4m3(f.w * 8.f, f.z * 8.f);
        w[q] = (uint32_t)lo | ((uint32_t)hi << 16);
    }
    uint4 u; u.x = w[0]; u.y = w[1]; u.z = w[2]; u.w = w[3];
    ((uint4*)(g_F8 + (size_t)i * D))[c] = u;
    if (idx < N_TOT) { g_pos[idx] = 0.f; g_tot[idx] = 0.f; }
}

// ---------------------------------------------------------------------------
// Kernel 2: upper-triangle symmetric FP8 GEMM, software-pipelined epilogue.
// Grid: 128 CTAs = 32 pairs x 4 chunks (each tile exactly once).
// ---------------------------------------------------------------------------
extern __shared__ char smem[];

__global__ void __launch_bounds__(256, 1)
gemm_kernel(const int* __restrict__ labels) {
    const uint32_t sb = smem_u32(smem);
    const int tid  = threadIdx.x;
    const int wid  = tid >> 5;
    const int lane = tid & 31;
    const int wm = wid >> 2;                 // 0..1 (64-row group)
    const int wn = wid & 3;                  // 0..3 (32-col group)

    // ---- schedule: pair p = (strip p, strip 63-p), 65 tiles, 4 chunks ----
    const int p  = blockIdx.x >> 2;          // 0..31
    const int ch = blockIdx.x & 3;
    const int s  = (ch == 0) ? 0 : 17 + 16 * (ch - 1);
    const int cnt = (ch == 0) ? 17 : 16;
    const int cntA = 64 - p;
    const int e = s + cnt;
    int sbi[2], sj0a[2], scnt[2], nseg = 0;
    if (s < cntA) {
        sbi[0] = p; sj0a[0] = p + s;
        scnt[0] = ((e < cntA) ? e : cntA) - s; nseg = 1;
    }
    if (e > cntA) {
        int st = (s > cntA) ? s : cntA;
        sbi[nseg] = 63 - p; sj0a[nseg] = (63 - p) + (st - cntA);
        scnt[nseg] = e - st; nseg++;
    }

    // ldmatrix per-lane address bases (fp8: 256B rows, 16B chunks)
    const int arow  = wm * 64 + (lane & 7) + ((lane >> 3) & 1) * 8;  // + mf*16
    const uint32_t a_base = sb + arow * 256;
    const int a_xor = arow & 7;
    const int a_hi  = lane >> 4;
    const int lb16  = lane & 15;
    const int b_hi  = (lb16 >> 3) & 1;
    const int brow_l = lb16 & 7;

    for (int sg = 0; sg < nseg; sg++) {
        const int bi   = sbi[sg];
        const int i0   = bi * TILE;
        const int nt   = scnt[sg];
        const int sj0v = sj0a[sg];
        const bool diag0 = (sj0v == bi);

        // per-thread row labels + row accumulators for this strip segment
        int   li[4][2];
        float atot[4][2], apos[4][2];
        #pragma unroll
        for (int mf = 0; mf < 4; mf++)
            #pragma unroll
            for (int h = 0; h < 2; h++) {
                int r = i0 + wm * 64 + mf * 16 + (lane >> 2) + h * 8;
                li[mf][h] = labels[r & (BSZ - 1)];
                atot[mf][h] = 0.f; apos[mf][h] = 0.f;
            }

        // prologue: A strip + B(tile0) + labels slot 0
        cp_tile(sb, g_F8 + (size_t)i0 * D, tid);
        {
            int j0f = sj0v * TILE;
            cp_tile(sb + OFF_B0, g_F8 + (size_t)j0f * D, tid);
            if (tid < 32) cp16(sb + OFF_LRING + tid * 16,
                               labels + (j0f & (BSZ - 1)) + tid * 4);
        }
        cp_commit();

        float cA[4][4][4], cB[4][4][4];

        // one (mf,nf) epilogue unit of the DEFERRED tile
        auto epi_unit = [&](const float (&CE)[4][4][4], int mf, int nf,
                            int pslot, bool pdiag,
                            float (&ctt)[4][2], float (&cpp)[4][2]) {
            const int col0 = wn * 32 + nf * 8 + (lane & 3) * 2;
            const int* lr = (const int*)(smem + OFF_LRING + pslot * 512);
            const int l0 = lr[col0], l1 = lr[col0 + 1];
            float e00 = fexp2(CE[mf][nf][0] * K2E8);
            float e01 = fexp2(CE[mf][nf][1] * K2E8);
            float e10 = fexp2(CE[mf][nf][2] * K2E8);
            float e11 = fexp2(CE[mf][nf][3] * K2E8);
            if (pdiag) {
                const int r0 = wm * 64 + mf * 16 + (lane >> 2);
                const int r1 = r0 + 8;
                if (r0 == col0)     e00 = 0.f;
                if (r0 == col0 + 1) e01 = 0.f;
                if (r1 == col0)     e10 = 0.f;
                if (r1 == col0 + 1) e11 = 0.f;
            }
            const bool m00 = (l0 == li[mf][0]), m01 = (l1 == li[mf][0]);
            const bool m10 = (l0 == li[mf][1]), m11 = (l1 == li[mf][1]);
            atot[mf][0] += e00 + e01;
            atot[mf][1] += e10 + e11;
            apos[mf][0] += (m00 ? e00 : 0.f) + (m01 ? e01 : 0.f);
            apos[mf][1] += (m10 ? e10 : 0.f) + (m11 ? e11 : 0.f);
            ctt[nf][0] += e00 + e10;
            ctt[nf][1] += e01 + e11;
            cpp[nf][0] += (m00 ? e00 : 0.f) + (m10 ? e10 : 0.f);
            cpp[nf][1] += (m01 ? e01 : 0.f) + (m11 ? e11 : 0.f);
        };

        auto col_flush = [&](int pj0, float (&ctt)[4][2], float (&cpp)[4][2]) {
            #pragma unroll
            for (int nf = 0; nf < 4; nf++)
                #pragma unroll
                for (int q = 0; q < 2; q++) {
                    float t2 = ctt[nf][q], p2 = cpp[nf][q];
                    t2 += __shfl_xor_sync(0xffffffffu, t2, 4);
                    t2 += __shfl_xor_sync(0xffffffffu, t2, 8);
                    t2 += __shfl_xor_sync(0xffffffffu, t2, 16);
                    p2 += __shfl_xor_sync(0xffffffffu, p2, 4);
                    p2 += __shfl_xor_sync(0xffffffffu, p2, 8);
                    p2 += __shfl_xor_sync(0xffffffffu, p2, 16);
                    if (lane < 4) {
                        int col = pj0 + wn * 32 + nf * 8 + lane * 2 + q;
                        atomicAdd(&g_tot[col], t2);
                        atomicAdd(&g_pos[col], p2);
                    }
                }
        };

        // one pipeline step: prefetch t+1, MMA(t)->CW, epilogue(t-1) from CE
        auto do_step = [&](int T, float (&CW)[4][4][4], float (&CE)[4][4][4],
                           bool doepi) {
            const int buf = T & 1;
            if (T + 1 < nt) {
                int j0n = (sj0v + T + 1) * TILE;
                cp_tile(sb + (buf ? OFF_B0 : OFF_B1), g_F8 + (size_t)j0n * D, tid);
                if (tid < 32) cp16(sb + OFF_LRING + ((T + 1) & 3) * 512 + tid * 16,
                                   labels + (j0n & (BSZ - 1)) + tid * 4);
                cp_commit();
                cp_wait<1>();
            } else {
                cp_wait<0>();
            }
            __syncthreads();

            const uint32_t b_s = sb + (buf ? OFF_B1 : OFF_B0);
            #pragma unroll
            for (int mf = 0; mf < 4; mf++)
                #pragma unroll
                for (int nf = 0; nf < 4; nf++)
                    #pragma unroll
                    for (int q = 0; q < 4; q++) CW[mf][nf][q] = 0.f;

            float ctt[4][2] = {}, cpp[4][2] = {};
            const int  pj0   = (sj0v + T - 1) * TILE;
            const bool pdiag = (T - 1 == 0) && diag0;
            const int  pslot = (T - 1) & 3;

            #pragma unroll
            for (int kc = 0; kc < 8; kc++) {     // K=256, 32 per mma
                uint32_t af[4][4], bf[4][2];
                #pragma unroll
                for (int mf = 0; mf < 4; mf++) {
                    uint32_t addr = a_base + mf * (16 * 256)
                                  + ((((kc << 1) + a_hi) ^ a_xor) << 4);
                    ldsm4(af[mf], addr);
                }
                #pragma unroll
                for (int nf = 0; nf < 4; nf++) {
                    int brow = wn * 32 + nf * 8 + brow_l;
                    uint32_t addr = b_s + brow * 256
                                  + ((((kc << 1) + b_hi) ^ (brow & 7)) << 4);
                    ldsm2(bf[nf], addr);
                }
                #pragma unroll
                for (int mf = 0; mf < 4; mf++)
                    #pragma unroll
                    for (int nf = 0; nf < 4; nf++)
                        mma_e4m3(CW[mf][nf], af[mf], bf[nf]);
                // 2 deferred epilogue units per kc step (16 over 8 steps)
                if (doepi) {
                    int u0 = kc * 2, u1 = kc * 2 + 1;
                    epi_unit(CE, u0 >> 2, u0 & 3, pslot, pdiag, ctt, cpp);
                    epi_unit(CE, u1 >> 2, u1 & 3, pslot, pdiag, ctt, cpp);
                }
            }
            if (doepi && !pdiag) col_flush(pj0, ctt, cpp);
            __syncthreads();
        };

        // standalone epilogue for the final tile of the segment
        auto drain = [&](const float (&CE)[4][4][4]) {
            float ctt[4][2] = {}, cpp[4][2] = {};
            const int  pj0   = (sj0v + nt - 1) * TILE;
            const bool pdiag = (nt - 1 == 0) && diag0;
            const int  pslot = (nt - 1) & 3;
            #pragma unroll
            for (int u = 0; u < 16; u++)
                epi_unit(CE, u >> 2, u & 3, pslot, pdiag, ctt, cpp);
            if (!pdiag) col_flush(pj0, ctt, cpp);
        };

        // pipeline: t=0 has no deferred epilogue; banks alternate statically
        do_step(0, cA, cB, false);
        int t = 1;
        for (; t + 1 < nt; t += 2) {
            do_step(t,     cB, cA, true);
            do_step(t + 1, cA, cB, true);
        }
        if (t < nt) do_step(t, cB, cA, true);
        if ((nt - 1) & 1) drain(cB); else drain(cA);

        // row flush for this strip segment
        #pragma unroll
        for (int mf = 0; mf < 4; mf++)
            #pragma unroll
            for (int h = 0; h < 2; h++) {
                float tt = atot[mf][h], pp = apos[mf][h];
                tt += __shfl_xor_sync(0xffffffffu, tt, 1);
                tt += __shfl_xor_sync(0xffffffffu, tt, 2);
                pp += __shfl_xor_sync(0xffffffffu, pp, 1);
                pp += __shfl_xor_sync(0xffffffffu, pp, 2);
                if ((lane & 3) == mf) {
                    int r = i0 + wm * 64 + mf * 16 + (lane >> 2) + h * 8;
                    atomicAdd(&g_tot[r], tt);
                    atomicAdd(&g_pos[r], pp);
                }
            }
        __syncthreads();   // segment done before A/B buffers reused
    }
}

// ---------------------------------------------------------------------------
// Kernel 3: loss = -mean(log((pos + eps*tot)/tot))
// ---------------------------------------------------------------------------
__global__ void finalize_kernel(float* __restrict__ out) {
    __shared__ float red[256];
    float s = 0.f;
    for (int i = threadIdx.x; i < N_TOT; i += 256) {
        float t = g_tot[i];
        float p = g_pos[i] + EPS_ * t;
        s += logf(p / t);
    }
    red[threadIdx.x] = s;
    __syncthreads();
    for (int st = 128; st; st >>= 1) {
        if (threadIdx.x < st) red[threadIdx.x] += red[threadIdx.x + st];
        __syncthreads();
    }
    if (threadIdx.x == 0) out[0] = -red[0] / (float)N_TOT;
}

// ---------------------------------------------------------------------------
extern "C" void kernel_launch(void* const* d_in, const int* in_sizes, int n_in,
                              void* d_out, int out_size) {
    const float* feats  = (const float*)d_in[0];
    const int*   labels = (const int*)d_in[1];
    float*       out    = (float*)d_out;

    prep_kernel<<<512, 256>>>(feats);

    cudaFuncSetAttribute(gemm_kernel, cudaFuncAttributeMaxDynamicSharedMemorySize, SMEM_TOTAL);
    gemm_kernel<<<128, 256, SMEM_TOTAL>>>(labels);

    finalize_kernel<<<1, 256>>>(out);
}

// round 14
// speedup vs baseline: 1.0144x; 1.0144x over previous
#include <cuda_runtime.h>
#include <cuda_bf16.h>
#include <cstdint>

#define N_TOT 8192
#define BSZ   4096
#define D     256
#define TILE  128
#define EPS_  1e-7f
// dot of 128x-scaled s8 vectors = 16384*S; exp(S/T) = exp2(dot * log2(e)/(0.07*16384))
#define K2I8  1.2579302e-3f

// smem: A strip 32KB | B0 32KB | B1 32KB | label ring 4 x 512B
#define OFF_B0     32768
#define OFF_B1     65536
#define OFF_LRING  98304
#define SMEM_TOTAL 100352

__device__ int8_t g_F8[N_TOT * D];    // s8, features pre-scaled by 128
__device__ float g_pos[N_TOT];
__device__ float g_tot[N_TOT];

// ---------------------------------------------------------------------------
// helpers
// ---------------------------------------------------------------------------
__device__ __forceinline__ uint32_t smem_u32(const void* p) {
    uint32_t a;
    asm("{ .reg .u64 t; cvta.to.shared.u64 t, %1; cvt.u32.u64 %0, t; }" : "=r"(a) : "l"(p));
    return a;
}
__device__ __forceinline__ void cp16(uint32_t s, const void* g) {
    asm volatile("cp.async.cg.shared.global [%0], [%1], 16;" :: "r"(s), "l"(g) : "memory");
}
__device__ __forceinline__ void cp_commit() {
    asm volatile("cp.async.commit_group;" ::: "memory");
}
template <int N> __device__ __forceinline__ void cp_wait() {
    asm volatile("cp.async.wait_group %0;" :: "n"(N) : "memory");
}
__device__ __forceinline__ void ldsm4(uint32_t* r, uint32_t addr) {
    asm volatile("ldmatrix.sync.aligned.m8n8.x4.shared.b16 {%0,%1,%2,%3}, [%4];"
                 : "=r"(r[0]), "=r"(r[1]), "=r"(r[2]), "=r"(r[3]) : "r"(addr));
}
__device__ __forceinline__ void ldsm2(uint32_t* r, uint32_t addr) {
    asm volatile("ldmatrix.sync.aligned.m8n8.x2.shared.b16 {%0,%1}, [%2];"
                 : "=r"(r[0]), "=r"(r[1]) : "r"(addr));
}
// INT8 IMMA: m16n8k32, s32 accum (Turing-era legacy-pipe instruction)
__device__ __forceinline__ void mma_s8(int* c, const uint32_t* a, const uint32_t* b) {
    asm volatile(
        "mma.sync.aligned.m16n8k32.row.col.s32.s8.s8.s32 "
        "{%0,%1,%2,%3}, {%4,%5,%6,%7}, {%8,%9}, {%0,%1,%2,%3};"
        : "+r"(c[0]), "+r"(c[1]), "+r"(c[2]), "+r"(c[3])
        : "r"(a[0]), "r"(a[1]), "r"(a[2]), "r"(a[3]), "r"(b[0]), "r"(b[1]));
}
__device__ __forceinline__ float fexp2(float x) {
    float y;
    asm("ex2.approx.f32 %0, %1;" : "=f"(y) : "f"(x));
    return y;
}
// pack 4 s32 -> 4 saturated s8 bytes (byte0 = x0)
__device__ __forceinline__ uint32_t pack_s8x4(int x0, int x1, int x2, int x3) {
    uint32_t t, d;
    asm("cvt.pack.sat.s8.s32.b32 %0, %1, %2, 0;" : "=r"(t) : "r"(x3), "r"(x2));
    asm("cvt.pack.sat.s8.s32.b32 %0, %1, %2, %3;" : "=r"(d) : "r"(x1), "r"(x0), "r"(t));
    return d;
}

// stage 128x256B s8 tile; XOR swizzle: 16B chunk c (0..15) of row r -> c^(r&7)
__device__ __forceinline__ void cp_tile(uint32_t dst, const int8_t* src, int tid) {
    #pragma unroll
    for (int it = 0; it < 8; it++) {
        int idx = it * 256 + tid;            // 0..2047 chunks
        int r = idx >> 4, c = idx & 15;
        uint32_t d = dst + r * 256 + ((c ^ (r & 7)) << 4);
        cp16(d, src + idx * 16);
    }
}

// ---------------------------------------------------------------------------
// Kernel 1: repack fp32 [bsz,2,d] -> s8 contrast rows [n,d] (x128); zero accums
// ---------------------------------------------------------------------------
__global__ void prep_kernel(const float* __restrict__ feats) {
    int idx = blockIdx.x * 256 + threadIdx.x;   // 0..131071, one 16B out chunk
    int i = idx >> 4;                           // row 0..8191
    int c = idx & 15;
    int v = i >> 12;
    int b = i & (BSZ - 1);
    const float4* src = (const float4*)(feats + (size_t)(b * 2 + v) * D + c * 16);
    uint32_t w[4];
    #pragma unroll
    for (int q = 0; q < 4; q++) {
        float4 f = src[q];
        w[q] = pack_s8x4(__float2int_rn(f.x * 128.f), __float2int_rn(f.y * 128.f),
                         __float2int_rn(f.z * 128.f), __float2int_rn(f.w * 128.f));
    }
    uint4 u; u.x = w[0]; u.y = w[1]; u.z = w[2]; u.w = w[3];
    ((uint4*)(g_F8 + (size_t)i * D))[c] = u;
    if (idx < N_TOT) { g_pos[idx] = 0.f; g_tot[idx] = 0.f; }
}

// ---------------------------------------------------------------------------
// Kernel 2: upper-triangle symmetric INT8 GEMM, software-pipelined epilogue.
// Grid: 128 CTAs = 32 pairs x 4 chunks (each tile exactly once).
// ---------------------------------------------------------------------------
extern __shared__ char smem[];

__global__ void __launch_bounds__(256, 1)
gemm_kernel(const int* __restrict__ labels) {
    const uint32_t sb = smem_u32(smem);
    const int tid  = threadIdx.x;
    const int wid  = tid >> 5;
    const int lane = tid & 31;
    const int wm = wid >> 2;                 // 0..1 (64-row group)
    const int wn = wid & 3;                  // 0..3 (32-col group)

    // ---- schedule: pair p = (strip p, strip 63-p), 65 tiles, 4 chunks ----
    const int p  = blockIdx.x >> 2;          // 0..31
    const int ch = blockIdx.x & 3;
    const int s  = (ch == 0) ? 0 : 17 + 16 * (ch - 1);
    const int cnt = (ch == 0) ? 17 : 16;
    const int cntA = 64 - p;
    const int e = s + cnt;
    int sbi[2], sj0a[2], scnt[2], nseg = 0;
    if (s < cntA) {
        sbi[0] = p; sj0a[0] = p + s;
        scnt[0] = ((e < cntA) ? e : cntA) - s; nseg = 1;
    }
    if (e > cntA) {
        int st = (s > cntA) ? s : cntA;
        sbi[nseg] = 63 - p; sj0a[nseg] = (63 - p) + (st - cntA);
        scnt[nseg] = e - st; nseg++;
    }

    // ldmatrix per-lane address bases (s8: 256B rows, 16B chunks)
    const int arow  = wm * 64 + (lane & 7) + ((lane >> 3) & 1) * 8;  // + mf*16
    const uint32_t a_base = sb + arow * 256;
    const int a_xor = arow & 7;
    const int a_hi  = lane >> 4;
    const int lb16  = lane & 15;
    const int b_hi  = (lb16 >> 3) & 1;
    const int brow_l = lb16 & 7;

    for (int sg = 0; sg < nseg; sg++) {
        const int bi   = sbi[sg];
        const int i0   = bi * TILE;
        const int nt   = scnt[sg];
        const int sj0v = sj0a[sg];
        const bool diag0 = (sj0v == bi);

        // per-thread row labels + row accumulators for this strip segment
        int   li[4][2];
        float atot[4][2], apos[4][2];
        #pragma unroll
        for (int mf = 0; mf < 4; mf++)
            #pragma unroll
            for (int h = 0; h < 2; h++) {
                int r = i0 + wm * 64 + mf * 16 + (lane >> 2) + h * 8;
                li[mf][h] = labels[r & (BSZ - 1)];
                atot[mf][h] = 0.f; apos[mf][h] = 0.f;
            }

        // prologue: A strip + B(tile0) + labels slot 0
        cp_tile(sb, g_F8 + (size_t)i0 * D, tid);
        {
            int j0f = sj0v * TILE;
            cp_tile(sb + OFF_B0, g_F8 + (size_t)j0f * D, tid);
            if (tid < 32) cp16(sb + OFF_LRING + tid * 16,
                               labels + (j0f & (BSZ - 1)) + tid * 4);
        }
        cp_commit();

        int cA[4][4][4], cB[4][4][4];

        // one (mf,nf) epilogue unit of the DEFERRED tile
        auto epi_unit = [&](const int (&CE)[4][4][4], int mf, int nf,
                            int pslot, bool pdiag,
                            float (&ctt)[4][2], float (&cpp)[4][2]) {
            const int col0 = wn * 32 + nf * 8 + (lane & 3) * 2;
            const int* lr = (const int*)(smem + OFF_LRING + pslot * 512);
            const int l0 = lr[col0], l1 = lr[col0 + 1];
            float e00 = fexp2((float)CE[mf][nf][0] * K2I8);
            float e01 = fexp2((float)CE[mf][nf][1] * K2I8);
            float e10 = fexp2((float)CE[mf][nf][2] * K2I8);
            float e11 = fexp2((float)CE[mf][nf][3] * K2I8);
            if (pdiag) {
                const int r0 = wm * 64 + mf * 16 + (lane >> 2);
                const int r1 = r0 + 8;
                if (r0 == col0)     e00 = 0.f;
                if (r0 == col0 + 1) e01 = 0.f;
                if (r1 == col0)     e10 = 0.f;
                if (r1 == col0 + 1) e11 = 0.f;
            }
            const bool m00 = (l0 == li[mf][0]), m01 = (l1 == li[mf][0]);
            const bool m10 = (l0 == li[mf][1]), m11 = (l1 == li[mf][1]);
            atot[mf][0] += e00 + e01;
            atot[mf][1] += e10 + e11;
            apos[mf][0] += (m00 ? e00 : 0.f) + (m01 ? e01 : 0.f);
            apos[mf][1] += (m10 ? e10 : 0.f) + (m11 ? e11 : 0.f);
            ctt[nf][0] += e00 + e10;
            ctt[nf][1] += e01 + e11;
            cpp[nf][0] += (m00 ? e00 : 0.f) + (m10 ? e10 : 0.f);
            cpp[nf][1] += (m01 ? e01 : 0.f) + (m11 ? e11 : 0.f);
        };

        auto col_flush = [&](int pj0, float (&ctt)[4][2], float (&cpp)[4][2]) {
            #pragma unroll
            for (int nf = 0; nf < 4; nf++)
                #pragma unroll
                for (int q = 0; q < 2; q++) {
                    float t2 = ctt[nf][q], p2 = cpp[nf][q];
                    t2 += __shfl_xor_sync(0xffffffffu, t2, 4);
                    t2 += __shfl_xor_sync(0xffffffffu, t2, 8);
                    t2 += __shfl_xor_sync(0xffffffffu, t2, 16);
                    p2 += __shfl_xor_sync(0xffffffffu, p2, 4);
                    p2 += __shfl_xor_sync(0xffffffffu, p2, 8);
                    p2 += __shfl_xor_sync(0xffffffffu, p2, 16);
                    if (lane < 4) {
                        int col = pj0 + wn * 32 + nf * 8 + lane * 2 + q;
                        atomicAdd(&g_tot[col], t2);
                        atomicAdd(&g_pos[col], p2);
                    }
                }
        };

        // one pipeline step: prefetch t+1, MMA(t)->CW, epilogue(t-1) from CE
        auto do_step = [&](int T, int (&CW)[4][4][4], int (&CE)[4][4][4],
                           bool doepi) {
            const int buf = T & 1;
            if (T + 1 < nt) {
                int j0n = (sj0v + T + 1) * TILE;
                cp_tile(sb + (buf ? OFF_B0 : OFF_B1), g_F8 + (size_t)j0n * D, tid);
                if (tid < 32) cp16(sb + OFF_LRING + ((T + 1) & 3) * 512 + tid * 16,
                                   labels + (j0n & (BSZ - 1)) + tid * 4);
                cp_commit();
                cp_wait<1>();
            } else {
                cp_wait<0>();
            }
            __syncthreads();

            const uint32_t b_s = sb + (buf ? OFF_B1 : OFF_B0);
            #pragma unroll
            for (int mf = 0; mf < 4; mf++)
                #pragma unroll
                for (int nf = 0; nf < 4; nf++)
                    #pragma unroll
                    for (int q = 0; q < 4; q++) CW[mf][nf][q] = 0;

            float ctt[4][2] = {}, cpp[4][2] = {};
            const int  pj0   = (sj0v + T - 1) * TILE;
            const bool pdiag = (T - 1 == 0) && diag0;
            const int  pslot = (T - 1) & 3;

            #pragma unroll
            for (int kc = 0; kc < 8; kc++) {     // K=256, 32 per mma
                uint32_t af[4][4], bf[4][2];
                #pragma unroll
                for (int mf = 0; mf < 4; mf++) {
                    uint32_t addr = a_base + mf * (16 * 256)
                                  + ((((kc << 1) + a_hi) ^ a_xor) << 4);
                    ldsm4(af[mf], addr);
                }
                #pragma unroll
                for (int nf = 0; nf < 4; nf++) {
                    int brow = wn * 32 + nf * 8 + brow_l;
                    uint32_t addr = b_s + brow * 256
                                  + ((((kc << 1) + b_hi) ^ (brow & 7)) << 4);
                    ldsm2(bf[nf], addr);
                }
                #pragma unroll
                for (int mf = 0; mf < 4; mf++)
                    #pragma unroll
                    for (int nf = 0; nf < 4; nf++)
                        mma_s8(CW[mf][nf], af[mf], bf[nf]);
                // 2 deferred epilogue units per kc step (16 over 8 steps)
                if (doepi) {
                    int u0 = kc * 2, u1 = kc * 2 + 1;
                    epi_unit(CE, u0 >> 2, u0 & 3, pslot, pdiag, ctt, cpp);
                    epi_unit(CE, u1 >> 2, u1 & 3, pslot, pdiag, ctt, cpp);
                }
            }
            if (doepi && !pdiag) col_flush(pj0, ctt, cpp);
            __syncthreads();
        };

        // standalone epilogue for the final tile of the segment
        auto drain = [&](const int (&CE)[4][4][4]) {
            float ctt[4][2] = {}, cpp[4][2] = {};
            const int  pj0   = (sj0v + nt - 1) * TILE;
            const bool pdiag = (nt - 1 == 0) && diag0;
            const int  pslot = (nt - 1) & 3;
            #pragma unroll
            for (int u = 0; u < 16; u++)
                epi_unit(CE, u >> 2, u & 3, pslot, pdiag, ctt, cpp);
            if (!pdiag) col_flush(pj0, ctt, cpp);
        };

        // pipeline: t=0 has no deferred epilogue; banks alternate statically
        do_step(0, cA, cB, false);
        int t = 1;
        for (; t + 1 < nt; t += 2) {
            do_step(t,     cB, cA, true);
            do_step(t + 1, cA, cB, true);
        }
        if (t < nt) do_step(t, cB, cA, true);
        if ((nt - 1) & 1) drain(cB); else drain(cA);

        // row flush for this strip segment
        #pragma unroll
        for (int mf = 0; mf < 4; mf++)
            #pragma unroll
            for (int h = 0; h < 2; h++) {
                float tt = atot[mf][h], pp = apos[mf][h];
                tt += __shfl_xor_sync(0xffffffffu, tt, 1);
                tt += __shfl_xor_sync(0xffffffffu, tt, 2);
                pp += __shfl_xor_sync(0xffffffffu, pp, 1);
                pp += __shfl_xor_sync(0xffffffffu, pp, 2);
                if ((lane & 3) == mf) {
                    int r = i0 + wm * 64 + mf * 16 + (lane >> 2) + h * 8;
                    atomicAdd(&g_tot[r], tt);
                    atomicAdd(&g_pos[r], pp);
                }
            }
        __syncthreads();   // segment done before A/B buffers reused
    }
}

// ---------------------------------------------------------------------------
// Kernel 3: loss = -mean(log((pos + eps*tot)/tot))
// ---------------------------------------------------------------------------
__global__ void finalize_kernel(float* __restrict__ out) {
    __shared__ float red[256];
    float s = 0.f;
    for (int i = threadIdx.x; i < N_TOT; i += 256) {
        float t = g_tot[i];
        float p = g_pos[i] + EPS_ * t;
        s += logf(p / t);
    }
    red[threadIdx.x] = s;
    __syncthreads();
    for (int st = 128; st; st >>= 1) {
        if (threadIdx.x < st) red[threadIdx.x] += red[threadIdx.x + st];
        __syncthreads();
    }
    if (threadIdx.x == 0) out[0] = -red[0] / (float)N_TOT;
}

// ---------------------------------------------------------------------------
extern "C" void kernel_launch(void* const* d_in, const int* in_sizes, int n_in,
                              void* d_out, int out_size) {
    const float* feats  = (const float*)d_in[0];
    const int*   labels = (const int*)d_in[1];
    float*       out    = (float*)d_out;

    prep_kernel<<<512, 256>>>(feats);

    cudaFuncSetAttribute(gemm_kernel, cudaFuncAttributeMaxDynamicSharedMemorySize, SMEM_TOTAL);
    gemm_kernel<<<128, 256, SMEM_TOTAL>>>(labels);

    finalize_kernel<<<1, 256>>>(out);
}

// round 15
// speedup vs baseline: 1.4674x; 1.4466x over previous
#include <cuda_runtime.h>
#include <cuda_bf16.h>
#include <cstdint>

#define N_TOT 8192
#define BSZ   4096
#define D     256
#define TILE  128
#define EPS_  1e-7f
#define K2EXP 20.60992915555661f   // log2(e) / 0.07

// smem: A strip 64KB | B0 64KB | B1 64KB | label ring 4 x 512B
#define OFF_B0     65536
#define OFF_B1     131072
#define OFF_LRING  196608
#define SMEM_TOTAL 198656

__device__ __nv_bfloat16 g_F[N_TOT * D];
__device__ float g_pos[N_TOT];
__device__ float g_tot[N_TOT];

// ---------------------------------------------------------------------------
// helpers
// ---------------------------------------------------------------------------
__device__ __forceinline__ uint32_t smem_u32(const void* p) {
    uint32_t a;
    asm("{ .reg .u64 t; cvta.to.shared.u64 t, %1; cvt.u32.u64 %0, t; }" : "=r"(a) : "l"(p));
    return a;
}
__device__ __forceinline__ void cp16(uint32_t s, const void* g) {
    asm volatile("cp.async.cg.shared.global [%0], [%1], 16;" :: "r"(s), "l"(g) : "memory");
}
__device__ __forceinline__ void cp_commit() {
    asm volatile("cp.async.commit_group;" ::: "memory");
}
template <int N> __device__ __forceinline__ void cp_wait() {
    asm volatile("cp.async.wait_group %0;" :: "n"(N) : "memory");
}
__device__ __forceinline__ void ldsm4(uint32_t* r, uint32_t addr) {
    asm volatile("ldmatrix.sync.aligned.m8n8.x4.shared.b16 {%0,%1,%2,%3}, [%4];"
                 : "=r"(r[0]), "=r"(r[1]), "=r"(r[2]), "=r"(r[3]) : "r"(addr));
}
__device__ __forceinline__ void ldsm2(uint32_t* r, uint32_t addr) {
    asm volatile("ldmatrix.sync.aligned.m8n8.x2.shared.b16 {%0,%1}, [%2];"
                 : "=r"(r[0]), "=r"(r[1]) : "r"(addr));
}
__device__ __forceinline__ void mma16816(float* c, const uint32_t* a, const uint32_t* b) {
    asm volatile(
        "mma.sync.aligned.m16n8k16.row.col.f32.bf16.bf16.f32 "
        "{%0,%1,%2,%3}, {%4,%5,%6,%7}, {%8,%9}, {%0,%1,%2,%3};"
        : "+f"(c[0]), "+f"(c[1]), "+f"(c[2]), "+f"(c[3])
        : "r"(a[0]), "r"(a[1]), "r"(a[2]), "r"(a[3]), "r"(b[0]), "r"(b[1]));
}
__device__ __forceinline__ float fexp2(float x) {
    float y;
    asm("ex2.approx.f32 %0, %1;" : "=f"(y) : "f"(x));
    return y;
}

// stage 128x256 bf16 tile; XOR swizzle: 16B chunk c of row r -> c ^ (r&7)
__device__ __forceinline__ void cp_tile(uint32_t dst, const __nv_bfloat16* src, int tid) {
    const char* s = (const char*)src;
    #pragma unroll
    for (int it = 0; it < 16; it++) {
        int idx = it * 256 + tid;
        int r = idx >> 5, c = idx & 31;
        uint32_t d = dst + r * 512 + ((c ^ (r & 7)) << 4);
        cp16(d, s + idx * 16);
    }
}

// ---------------------------------------------------------------------------
// Kernel 1: repack fp32 [bsz,2,d] -> bf16 contrast rows [n,d]; zero accums
// ---------------------------------------------------------------------------
__global__ void prep_kernel(const float* __restrict__ feats) {
    int base = (blockIdx.x * 256 + threadIdx.x) * 2;   // 2 consecutive 16B out chunks
    int i = base >> 5;
    int c = base & 31;
    int v = i >> 12;
    int b = i & (BSZ - 1);
    const float4* src = (const float4*)(feats + (size_t)(b * 2 + v) * D + c * 8);
    float4 f0 = src[0], f1 = src[1], f2 = src[2], f3 = src[3];
    __nv_bfloat162 h0 = __floats2bfloat162_rn(f0.x, f0.y);
    __nv_bfloat162 h1 = __floats2bfloat162_rn(f0.z, f0.w);
    __nv_bfloat162 h2 = __floats2bfloat162_rn(f1.x, f1.y);
    __nv_bfloat162 h3 = __floats2bfloat162_rn(f1.z, f1.w);
    __nv_bfloat162 h4 = __floats2bfloat162_rn(f2.x, f2.y);
    __nv_bfloat162 h5 = __floats2bfloat162_rn(f2.z, f2.w);
    __nv_bfloat162 h6 = __floats2bfloat162_rn(f3.x, f3.y);
    __nv_bfloat162 h7 = __floats2bfloat162_rn(f3.z, f3.w);
    uint4 u0, u1;
    u0.x = *(uint32_t*)&h0; u0.y = *(uint32_t*)&h1;
    u0.z = *(uint32_t*)&h2; u0.w = *(uint32_t*)&h3;
    u1.x = *(uint32_t*)&h4; u1.y = *(uint32_t*)&h5;
    u1.z = *(uint32_t*)&h6; u1.w = *(uint32_t*)&h7;
    uint4* dst = (uint4*)(g_F + (size_t)i * D);
    dst[c] = u0;
    dst[c + 1] = u1;
    int z = blockIdx.x * 256 + threadIdx.x;
    if (z < N_TOT) { g_pos[z] = 0.f; g_tot[z] = 0.f; }
}

// ---------------------------------------------------------------------------
// Kernel 2: upper-triangle symmetric GEMM, software-pipelined epilogue.
// Grid: 148 CTAs; all 2080 tiles flattened into one global index space,
// each CTA takes a contiguous range (8 CTAs x 15 tiles + 140 x 14 = 2080).
// Global tile g: pair p = g/65, offset o = g%65.
// Pair p = strips {p, 63-p}: first 64-p tiles are strip p (j = p+o),
// remaining p+1 tiles are strip 63-p (j = 63-p + (o-(64-p))).
// ---------------------------------------------------------------------------
extern __shared__ char smem[];

__global__ void __launch_bounds__(256, 1)
gemm_kernel(const int* __restrict__ labels) {
    const uint32_t sb = smem_u32(smem);
    const int tid  = threadIdx.x;
    const int wid  = tid >> 5;
    const int lane = tid & 31;
    const int wm = wid >> 2;                 // 0..1 (64-row group)
    const int wn = wid & 3;                  // 0..3 (32-col group)

    // contiguous global tile range for this CTA
    const int cta = blockIdx.x;              // 0..147
    const int extra = (cta < 8) ? cta : 8;
    int g0 = cta * 14 + extra;
    int g1 = g0 + 14 + ((cta < 8) ? 1 : 0);

    // ldmatrix per-lane address bases
    const int arow  = wm * 64 + (lane & 7) + ((lane >> 3) & 1) * 8;  // + mf*16
    const uint32_t a_base = sb + arow * 512;
    const int a_xor = arow & 7;
    const int a_hi  = lane >> 4;
    const int lb16  = lane & 15;
    const int b_hi  = (lb16 >> 3) & 1;
    const int brow_l = lb16 & 7;

    while (g0 < g1) {
        const int p = g0 / 65;
        const int o = g0 - p * 65;
        const int take = min(g1 - g0, 65 - o);
        g0 += take;

        // split this pair-chunk into <=2 strip segments
        const int cntA = 64 - p;
        const int e = o + take;
        int sbi[2], sj0a[2], scnt[2], nseg = 0;
        if (o < cntA) {
            sbi[0] = p; sj0a[0] = p + o;
            scnt[0] = ((e < cntA) ? e : cntA) - o; nseg = 1;
        }
        if (e > cntA) {
            int st = (o > cntA) ? o : cntA;
            sbi[nseg] = 63 - p; sj0a[nseg] = (63 - p) + (st - cntA);
            scnt[nseg] = e - st; nseg++;
        }

        for (int sg = 0; sg < nseg; sg++) {
            const int bi   = sbi[sg];
            const int i0   = bi * TILE;
            const int nt   = scnt[sg];
            const int sj0v = sj0a[sg];
            const bool diag0 = (sj0v == bi);

            // per-thread row labels + row accumulators for this strip segment
            int   li[4][2];
            float atot[4][2], apos[4][2];
            #pragma unroll
            for (int mf = 0; mf < 4; mf++)
                #pragma unroll
                for (int h = 0; h < 2; h++) {
                    int r = i0 + wm * 64 + mf * 16 + (lane >> 2) + h * 8;
                    li[mf][h] = labels[r & (BSZ - 1)];
                    atot[mf][h] = 0.f; apos[mf][h] = 0.f;
                }

            // prologue: A strip + B(tile0) + labels slot 0
            cp_tile(sb, g_F + (size_t)i0 * D, tid);
            {
                int j0f = sj0v * TILE;
                cp_tile(sb + OFF_B0, g_F + (size_t)j0f * D, tid);
                if (tid < 32) cp16(sb + OFF_LRING + tid * 16,
                                   labels + (j0f & (BSZ - 1)) + tid * 4);
            }
            cp_commit();

            float cA[4][4][4], cB[4][4][4];

            // one (mf,nf) epilogue unit of the DEFERRED tile
            auto epi_unit = [&](const float (&CE)[4][4][4], int mf, int nf,
                                int pslot, bool pdiag,
                                float (&ctt)[4][2], float (&cpp)[4][2]) {
                const int col0 = wn * 32 + nf * 8 + (lane & 3) * 2;
                const int* lr = (const int*)(smem + OFF_LRING + pslot * 512);
                const int l0 = lr[col0], l1 = lr[col0 + 1];
                float e00 = fexp2(CE[mf][nf][0] * K2EXP);
                float e01 = fexp2(CE[mf][nf][1] * K2EXP);
                float e10 = fexp2(CE[mf][nf][2] * K2EXP);
                float e11 = fexp2(CE[mf][nf][3] * K2EXP);
                if (pdiag) {
                    const int r0 = wm * 64 + mf * 16 + (lane >> 2);
                    const int r1 = r0 + 8;
                    if (r0 == col0)     e00 = 0.f;
                    if (r0 == col0 + 1) e01 = 0.f;
                    if (r1 == col0)     e10 = 0.f;
                    if (r1 == col0 + 1) e11 = 0.f;
                }
                const bool m00 = (l0 == li[mf][0]), m01 = (l1 == li[mf][0]);
                const bool m10 = (l0 == li[mf][1]), m11 = (l1 == li[mf][1]);
                atot[mf][0] += e00 + e01;
                atot[mf][1] += e10 + e11;
                apos[mf][0] += (m00 ? e00 : 0.f) + (m01 ? e01 : 0.f);
                apos[mf][1] += (m10 ? e10 : 0.f) + (m11 ? e11 : 0.f);
                ctt[nf][0] += e00 + e10;
                ctt[nf][1] += e01 + e11;
                cpp[nf][0] += (m00 ? e00 : 0.f) + (m10 ? e10 : 0.f);
                cpp[nf][1] += (m01 ? e01 : 0.f) + (m11 ? e11 : 0.f);
            };

            auto col_flush = [&](int pj0, float (&ctt)[4][2], float (&cpp)[4][2]) {
                #pragma unroll
                for (int nf = 0; nf < 4; nf++)
                    #pragma unroll
                    for (int q = 0; q < 2; q++) {
                        float t2 = ctt[nf][q], p2 = cpp[nf][q];
                        t2 += __shfl_xor_sync(0xffffffffu, t2, 4);
                        t2 += __shfl_xor_sync(0xffffffffu, t2, 8);
                        t2 += __shfl_xor_sync(0xffffffffu, t2, 16);
                        p2 += __shfl_xor_sync(0xffffffffu, p2, 4);
                        p2 += __shfl_xor_sync(0xffffffffu, p2, 8);
                        p2 += __shfl_xor_sync(0xffffffffu, p2, 16);
                        if (lane < 4) {
                            int col = pj0 + wn * 32 + nf * 8 + lane * 2 + q;
                            atomicAdd(&g_tot[col], t2);
                            atomicAdd(&g_pos[col], p2);
                        }
                    }
            };

            // one pipeline step: prefetch t+1, MMA(t)->CW, epilogue(t-1) from CE
            auto do_step = [&](int T, float (&CW)[4][4][4], float (&CE)[4][4][4],
                               bool doepi) {
                const int buf = T & 1;
                if (T + 1 < nt) {
                    int j0n = (sj0v + T + 1) * TILE;
                    cp_tile(sb + (buf ? OFF_B0 : OFF_B1), g_F + (size_t)j0n * D, tid);
                    if (tid < 32) cp16(sb + OFF_LRING + ((T + 1) & 3) * 512 + tid * 16,
                                       labels + (j0n & (BSZ - 1)) + tid * 4);
                    cp_commit();
                    cp_wait<1>();
                } else {
                    cp_wait<0>();
                }
                __syncthreads();

                const uint32_t b_s = sb + (buf ? OFF_B1 : OFF_B0);
                #pragma unroll
                for (int mf = 0; mf < 4; mf++)
                    #pragma unroll
                    for (int nf = 0; nf < 4; nf++)
                        #pragma unroll
                        for (int q = 0; q < 4; q++) CW[mf][nf][q] = 0.f;

                float ctt[4][2] = {}, cpp[4][2] = {};
                const int  pj0   = (sj0v + T - 1) * TILE;
                const bool pdiag = (T - 1 == 0) && diag0;
                const int  pslot = (T - 1) & 3;

                #pragma unroll
                for (int kc = 0; kc < 16; kc++) {
                    uint32_t af[4][4], bf[4][2];
                    #pragma unroll
                    for (int mf = 0; mf < 4; mf++) {
                        uint32_t addr = a_base + mf * (16 * 512)
                                      + ((((kc << 1) + a_hi) ^ a_xor) << 4);
                        ldsm4(af[mf], addr);
                    }
                    #pragma unroll
                    for (int nf = 0; nf < 4; nf++) {
                        int brow = wn * 32 + nf * 8 + brow_l;
                        uint32_t addr = b_s + brow * 512
                                      + ((((kc << 1) + b_hi) ^ (brow & 7)) << 4);
                        ldsm2(bf[nf], addr);
                    }
                    #pragma unroll
                    for (int mf = 0; mf < 4; mf++)
                        #pragma unroll
                        for (int nf = 0; nf < 4; nf++)
                            mma16816(CW[mf][nf], af[mf], bf[nf]);
                    // interleave one epilogue unit of the previous tile into
                    // the HMMA structural-stall shadow
                    if (doepi) epi_unit(CE, kc >> 2, kc & 3, pslot, pdiag, ctt, cpp);
                }
                if (doepi && !pdiag) col_flush(pj0, ctt, cpp);
                __syncthreads();
            };

            // standalone epilogue for the final tile of the segment
            auto drain = [&](const float (&CE)[4][4][4]) {
                float ctt[4][2] = {}, cpp[4][2] = {};
                const int  pj0   = (sj0v + nt - 1) * TILE;
                const bool pdiag = (nt - 1 == 0) && diag0;
                const int  pslot = (nt - 1) & 3;
                #pragma unroll
                for (int u = 0; u < 16; u++)
                    epi_unit(CE, u >> 2, u & 3, pslot, pdiag, ctt, cpp);
                if (!pdiag) col_flush(pj0, ctt, cpp);
            };

            // pipeline: t=0 has no deferred epilogue; banks alternate statically
            do_step(0, cA, cB, false);
            int t = 1;
            for (; t + 1 < nt; t += 2) {
                do_step(t,     cB, cA, true);
                do_step(t + 1, cA, cB, true);
            }
            if (t < nt) do_step(t, cB, cA, true);
            if ((nt - 1) & 1) drain(cB); else drain(cA);

            // row flush for this strip segment
            #pragma unroll
            for (int mf = 0; mf < 4; mf++)
                #pragma unroll
                for (int h = 0; h < 2; h++) {
                    float tt = atot[mf][h], pp = apos[mf][h];
                    tt += __shfl_xor_sync(0xffffffffu, tt, 1);
                    tt += __shfl_xor_sync(0xffffffffu, tt, 2);
                    pp += __shfl_xor_sync(0xffffffffu, pp, 1);
                    pp += __shfl_xor_sync(0xffffffffu, pp, 2);
                    if ((lane & 3) == mf) {
                        int r = i0 + wm * 64 + mf * 16 + (lane >> 2) + h * 8;
                        atomicAdd(&g_tot[r], tt);
                        atomicAdd(&g_pos[r], pp);
                    }
                }
            __syncthreads();   // segment done before A/B buffers reused
        }
    }
}

// ---------------------------------------------------------------------------
// Kernel 3: loss = -mean(log((pos + eps*tot)/tot))
// ---------------------------------------------------------------------------
__global__ void finalize_kernel(float* __restrict__ out) {
    __shared__ float red[256];
    float s = 0.f;
    for (int i = threadIdx.x; i < N_TOT; i += 256) {
        float t = g_tot[i];
        float p = g_pos[i] + EPS_ * t;
        s += logf(p / t);
    }
    red[threadIdx.x] = s;
    __syncthreads();
    for (int st = 128; st; st >>= 1) {
        if (threadIdx.x < st) red[threadIdx.x] += red[threadIdx.x + st];
        __syncthreads();
    }
    if (threadIdx.x == 0) out[0] = -red[0] / (float)N_TOT;
}

// ---------------------------------------------------------------------------
extern "C" void kernel_launch(void* const* d_in, const int* in_sizes, int n_in,
                              void* d_out, int out_size) {
    const float* feats  = (const float*)d_in[0];
    const int*   labels = (const int*)d_in[1];
    float*       out    = (float*)d_out;

    prep_kernel<<<512, 256>>>(feats);

    cudaFuncSetAttribute(gemm_kernel, cudaFuncAttributeMaxDynamicSharedMemorySize, SMEM_TOTAL);
    gemm_kernel<<<148, 256, SMEM_TOTAL>>>(labels);   // all SMs, balanced 14/15 tiles

    finalize_kernel<<<1, 256>>>(out);
}

// round 16
// speedup vs baseline: 2.2838x; 1.5563x over previous
#include <cuda_runtime.h>
#include <cuda_bf16.h>
#include <cstdint>

#define N_TOT 8192
#define BSZ   4096
#define D     256
#define TILE  128
#define EPS_  1e-7f
#define K2EXP 20.60992915555661f   // log2(e) / 0.07

// smem: A strip 64KB | B0 64KB | B1 64KB | label ring 4 x 512B
#define OFF_B0     65536
#define OFF_B1     131072
#define OFF_LRING  196608
#define SMEM_TOTAL 198656

__device__ __nv_bfloat16 g_F[N_TOT * D];
__device__ float g_pos[N_TOT];
__device__ float g_tot[N_TOT];

// ---------------------------------------------------------------------------
// helpers
// ---------------------------------------------------------------------------
__device__ __forceinline__ uint32_t smem_u32(const void* p) {
    uint32_t a;
    asm("{ .reg .u64 t; cvta.to.shared.u64 t, %1; cvt.u32.u64 %0, t; }" : "=r"(a) : "l"(p));
    return a;
}
__device__ __forceinline__ void cp16(uint32_t s, const void* g) {
    asm volatile("cp.async.cg.shared.global [%0], [%1], 16;" :: "r"(s), "l"(g) : "memory");
}
__device__ __forceinline__ void cp_commit() {
    asm volatile("cp.async.commit_group;" ::: "memory");
}
template <int N> __device__ __forceinline__ void cp_wait() {
    asm volatile("cp.async.wait_group %0;" :: "n"(N) : "memory");
}
__device__ __forceinline__ void ldsm4(uint32_t* r, uint32_t addr) {
    asm volatile("ldmatrix.sync.aligned.m8n8.x4.shared.b16 {%0,%1,%2,%3}, [%4];"
                 : "=r"(r[0]), "=r"(r[1]), "=r"(r[2]), "=r"(r[3]) : "r"(addr));
}
__device__ __forceinline__ void ldsm2(uint32_t* r, uint32_t addr) {
    asm volatile("ldmatrix.sync.aligned.m8n8.x2.shared.b16 {%0,%1}, [%2];"
                 : "=r"(r[0]), "=r"(r[1]) : "r"(addr));
}
__device__ __forceinline__ void mma16816(float* c, const uint32_t* a, const uint32_t* b) {
    asm volatile(
        "mma.sync.aligned.m16n8k16.row.col.f32.bf16.bf16.f32 "
        "{%0,%1,%2,%3}, {%4,%5,%6,%7}, {%8,%9}, {%0,%1,%2,%3};"
        : "+f"(c[0]), "+f"(c[1]), "+f"(c[2]), "+f"(c[3])
        : "r"(a[0]), "r"(a[1]), "r"(a[2]), "r"(a[3]), "r"(b[0]), "r"(b[1]));
}
__device__ __forceinline__ float fexp2(float x) {
    float y;
    asm("ex2.approx.f32 %0, %1;" : "=f"(y) : "f"(x));
    return y;
}

// stage 128x256 bf16 tile; XOR swizzle: 16B chunk c of row r -> c ^ (r&7)
__device__ __forceinline__ void cp_tile(uint32_t dst, const __nv_bfloat16* src, int tid) {
    const char* s = (const char*)src;
    #pragma unroll
    for (int it = 0; it < 16; it++) {
        int idx = it * 256 + tid;
        int r = idx >> 5, c = idx & 31;
        uint32_t d = dst + r * 512 + ((c ^ (r & 7)) << 4);
        cp16(d, s + idx * 16);
    }
}

// ---------------------------------------------------------------------------
// Kernel 1: repack fp32 [bsz,2,d] -> bf16 contrast rows [n,d]; zero accums
// ---------------------------------------------------------------------------
__global__ void prep_kernel(const float* __restrict__ feats) {
    int base = (blockIdx.x * 256 + threadIdx.x) * 2;   // 2 consecutive 16B out chunks
    int i = base >> 5;
    int c = base & 31;
    int v = i >> 12;
    int b = i & (BSZ - 1);
    const float4* src = (const float4*)(feats + (size_t)(b * 2 + v) * D + c * 8);
    float4 f0 = src[0], f1 = src[1], f2 = src[2], f3 = src[3];
    __nv_bfloat162 h0 = __floats2bfloat162_rn(f0.x, f0.y);
    __nv_bfloat162 h1 = __floats2bfloat162_rn(f0.z, f0.w);
    __nv_bfloat162 h2 = __floats2bfloat162_rn(f1.x, f1.y);
    __nv_bfloat162 h3 = __floats2bfloat162_rn(f1.z, f1.w);
    __nv_bfloat162 h4 = __floats2bfloat162_rn(f2.x, f2.y);
    __nv_bfloat162 h5 = __floats2bfloat162_rn(f2.z, f2.w);
    __nv_bfloat162 h6 = __floats2bfloat162_rn(f3.x, f3.y);
    __nv_bfloat162 h7 = __floats2bfloat162_rn(f3.z, f3.w);
    uint4 u0, u1;
    u0.x = *(uint32_t*)&h0; u0.y = *(uint32_t*)&h1;
    u0.z = *(uint32_t*)&h2; u0.w = *(uint32_t*)&h3;
    u1.x = *(uint32_t*)&h4; u1.y = *(uint32_t*)&h5;
    u1.z = *(uint32_t*)&h6; u1.w = *(uint32_t*)&h7;
    uint4* dst = (uint4*)(g_F + (size_t)i * D);
    dst[c] = u0;
    dst[c + 1] = u1;
    int z = blockIdx.x * 256 + threadIdx.x;
    if (z < N_TOT) { g_pos[z] = 0.f; g_tot[z] = 0.f; }
}

// ---------------------------------------------------------------------------
// Kernel 2: upper-triangle symmetric GEMM, software-pipelined epilogue.
// Grid: 148 CTAs; 2080 tiles flattened (8 CTAs x 15 + 140 x 14). Segment
// list is precomputed in a tiny scalar pre-pass (<=4 segments), then the
// round-8 segment loop runs unchanged (no dynamic outer loop around the
// accumulator banks).
// ---------------------------------------------------------------------------
extern __shared__ char smem[];

__global__ void __launch_bounds__(256, 1)
gemm_kernel(const int* __restrict__ labels) {
    const uint32_t sb = smem_u32(smem);
    const int tid  = threadIdx.x;
    const int wid  = tid >> 5;
    const int lane = tid & 31;
    const int wm = wid >> 2;                 // 0..1 (64-row group)
    const int wn = wid & 3;                  // 0..3 (32-col group)

    // ---- scalar pre-pass: contiguous global tile range -> <=4 segments ----
    int sbi[4], sj0a[4], scnt[4], nseg = 0;
    {
        const int cta = blockIdx.x;          // 0..147
        const int extra = (cta < 8) ? cta : 8;
        int g0 = cta * 14 + extra;
        int g1 = g0 + 14 + ((cta < 8) ? 1 : 0);
        while (g0 < g1) {
            int p = g0 / 65;
            int o = g0 - p * 65;
            int take = min(g1 - g0, 65 - o);
            int cntA = 64 - p;
            int e = o + take;
            if (o < cntA) {
                sbi[nseg] = p; sj0a[nseg] = p + o;
                scnt[nseg] = ((e < cntA) ? e : cntA) - o; nseg++;
            }
            if (e > cntA) {
                int st = (o > cntA) ? o : cntA;
                sbi[nseg] = 63 - p; sj0a[nseg] = (63 - p) + (st - cntA);
                scnt[nseg] = e - st; nseg++;
            }
            g0 += take;
        }
    }

    // ldmatrix per-lane address bases
    const int arow  = wm * 64 + (lane & 7) + ((lane >> 3) & 1) * 8;  // + mf*16
    const uint32_t a_base = sb + arow * 512;
    const int a_xor = arow & 7;
    const int a_hi  = lane >> 4;
    const int lb16  = lane & 15;
    const int b_hi  = (lb16 >> 3) & 1;
    const int brow_l = lb16 & 7;

    for (int sg = 0; sg < nseg; sg++) {
        const int bi   = sbi[sg];
        const int i0   = bi * TILE;
        const int nt   = scnt[sg];
        const int sj0v = sj0a[sg];
        const bool diag0 = (sj0v == bi);

        // per-thread row labels + row accumulators for this strip segment
        int   li[4][2];
        float atot[4][2], apos[4][2];
        #pragma unroll
        for (int mf = 0; mf < 4; mf++)
            #pragma unroll
            for (int h = 0; h < 2; h++) {
                int r = i0 + wm * 64 + mf * 16 + (lane >> 2) + h * 8;
                li[mf][h] = labels[r & (BSZ - 1)];
                atot[mf][h] = 0.f; apos[mf][h] = 0.f;
            }

        // prologue: A strip + B(tile0) + labels slot 0
        cp_tile(sb, g_F + (size_t)i0 * D, tid);
        {
            int j0f = sj0v * TILE;
            cp_tile(sb + OFF_B0, g_F + (size_t)j0f * D, tid);
            if (tid < 32) cp16(sb + OFF_LRING + tid * 16,
                               labels + (j0f & (BSZ - 1)) + tid * 4);
        }
        cp_commit();

        float cA[4][4][4], cB[4][4][4];

        // one (mf,nf) epilogue unit of the DEFERRED tile
        auto epi_unit = [&](const float (&CE)[4][4][4], int mf, int nf,
                            int pslot, bool pdiag,
                            float (&ctt)[4][2], float (&cpp)[4][2]) {
            const int col0 = wn * 32 + nf * 8 + (lane & 3) * 2;
            const int* lr = (const int*)(smem + OFF_LRING + pslot * 512);
            const int l0 = lr[col0], l1 = lr[col0 + 1];
            float e00 = fexp2(CE[mf][nf][0] * K2EXP);
            float e01 = fexp2(CE[mf][nf][1] * K2EXP);
            float e10 = fexp2(CE[mf][nf][2] * K2EXP);
            float e11 = fexp2(CE[mf][nf][3] * K2EXP);
            if (pdiag) {
                const int r0 = wm * 64 + mf * 16 + (lane >> 2);
                const int r1 = r0 + 8;
                if (r0 == col0)     e00 = 0.f;
                if (r0 == col0 + 1) e01 = 0.f;
                if (r1 == col0)     e10 = 0.f;
                if (r1 == col0 + 1) e11 = 0.f;
            }
            const bool m00 = (l0 == li[mf][0]), m01 = (l1 == li[mf][0]);
            const bool m10 = (l0 == li[mf][1]), m11 = (l1 == li[mf][1]);
            atot[mf][0] += e00 + e01;
            atot[mf][1] += e10 + e11;
            apos[mf][0] += (m00 ? e00 : 0.f) + (m01 ? e01 : 0.f);
            apos[mf][1] += (m10 ? e10 : 0.f) + (m11 ? e11 : 0.f);
            ctt[nf][0] += e00 + e10;
            ctt[nf][1] += e01 + e11;
            cpp[nf][0] += (m00 ? e00 : 0.f) + (m10 ? e10 : 0.f);
            cpp[nf][1] += (m01 ? e01 : 0.f) + (m11 ? e11 : 0.f);
        };

        auto col_flush = [&](int pj0, float (&ctt)[4][2], float (&cpp)[4][2]) {
            #pragma unroll
            for (int nf = 0; nf < 4; nf++)
                #pragma unroll
                for (int q = 0; q < 2; q++) {
                    float t2 = ctt[nf][q], p2 = cpp[nf][q];
                    t2 += __shfl_xor_sync(0xffffffffu, t2, 4);
                    t2 += __shfl_xor_sync(0xffffffffu, t2, 8);
                    t2 += __shfl_xor_sync(0xffffffffu, t2, 16);
                    p2 += __shfl_xor_sync(0xffffffffu, p2, 4);
                    p2 += __shfl_xor_sync(0xffffffffu, p2, 8);
                    p2 += __shfl_xor_sync(0xffffffffu, p2, 16);
                    if (lane < 4) {
                        int col = pj0 + wn * 32 + nf * 8 + lane * 2 + q;
                        atomicAdd(&g_tot[col], t2);
                        atomicAdd(&g_pos[col], p2);
                    }
                }
        };

        // one pipeline step: prefetch t+1, MMA(t)->CW, epilogue(t-1) from CE
        auto do_step = [&](int T, float (&CW)[4][4][4], float (&CE)[4][4][4],
                           bool doepi) {
            const int buf = T & 1;
            if (T + 1 < nt) {
                int j0n = (sj0v + T + 1) * TILE;
                cp_tile(sb + (buf ? OFF_B0 : OFF_B1), g_F + (size_t)j0n * D, tid);
                if (tid < 32) cp16(sb + OFF_LRING + ((T + 1) & 3) * 512 + tid * 16,
                                   labels + (j0n & (BSZ - 1)) + tid * 4);
                cp_commit();
                cp_wait<1>();
            } else {
                cp_wait<0>();
            }
            __syncthreads();

            const uint32_t b_s = sb + (buf ? OFF_B1 : OFF_B0);
            #pragma unroll
            for (int mf = 0; mf < 4; mf++)
                #pragma unroll
                for (int nf = 0; nf < 4; nf++)
                    #pragma unroll
                    for (int q = 0; q < 4; q++) CW[mf][nf][q] = 0.f;

            float ctt[4][2] = {}, cpp[4][2] = {};
            const int  pj0   = (sj0v + T - 1) * TILE;
            const bool pdiag = (T - 1 == 0) && diag0;
            const int  pslot = (T - 1) & 3;

            #pragma unroll
            for (int kc = 0; kc < 16; kc++) {
                uint32_t af[4][4], bf[4][2];
                #pragma unroll
                for (int mf = 0; mf < 4; mf++) {
                    uint32_t addr = a_base + mf * (16 * 512)
                                  + ((((kc << 1) + a_hi) ^ a_xor) << 4);
                    ldsm4(af[mf], addr);
                }
                #pragma unroll
                for (int nf = 0; nf < 4; nf++) {
                    int brow = wn * 32 + nf * 8 + brow_l;
                    uint32_t addr = b_s + brow * 512
                                  + ((((kc << 1) + b_hi) ^ (brow & 7)) << 4);
                    ldsm2(bf[nf], addr);
                }
                #pragma unroll
                for (int mf = 0; mf < 4; mf++)
                    #pragma unroll
                    for (int nf = 0; nf < 4; nf++)
                        mma16816(CW[mf][nf], af[mf], bf[nf]);
                // interleave one epilogue unit of the previous tile into the
                // HMMA structural-stall shadow
                if (doepi) epi_unit(CE, kc >> 2, kc & 3, pslot, pdiag, ctt, cpp);
            }
            if (doepi && !pdiag) col_flush(pj0, ctt, cpp);
            __syncthreads();
        };

        // standalone epilogue for the final tile of the segment
        auto drain = [&](const float (&CE)[4][4][4]) {
            float ctt[4][2] = {}, cpp[4][2] = {};
            const int  pj0   = (sj0v + nt - 1) * TILE;
            const bool pdiag = (nt - 1 == 0) && diag0;
            const int  pslot = (nt - 1) & 3;
            #pragma unroll
            for (int u = 0; u < 16; u++)
                epi_unit(CE, u >> 2, u & 3, pslot, pdiag, ctt, cpp);
            if (!pdiag) col_flush(pj0, ctt, cpp);
        };

        // pipeline: t=0 has no deferred epilogue; banks alternate statically
        do_step(0, cA, cB, false);
        int t = 1;
        for (; t + 1 < nt; t += 2) {
            do_step(t,     cB, cA, true);
            do_step(t + 1, cA, cB, true);
        }
        if (t < nt) do_step(t, cB, cA, true);
        if ((nt - 1) & 1) drain(cB); else drain(cA);

        // row flush for this strip segment
        #pragma unroll
        for (int mf = 0; mf < 4; mf++)
            #pragma unroll
            for (int h = 0; h < 2; h++) {
                float tt = atot[mf][h], pp = apos[mf][h];
                tt += __shfl_xor_sync(0xffffffffu, tt, 1);
                tt += __shfl_xor_sync(0xffffffffu, tt, 2);
                pp += __shfl_xor_sync(0xffffffffu, pp, 1);
                pp += __shfl_xor_sync(0xffffffffu, pp, 2);
                if ((lane & 3) == mf) {
                    int r = i0 + wm * 64 + mf * 16 + (lane >> 2) + h * 8;
                    atomicAdd(&g_tot[r], tt);
                    atomicAdd(&g_pos[r], pp);
                }
            }
        __syncthreads();   // segment done before A/B buffers reused
    }
}

// ---------------------------------------------------------------------------
// Kernel 3: loss = -mean(log((pos + eps*tot)/tot))
// ---------------------------------------------------------------------------
__global__ void finalize_kernel(float* __restrict__ out) {
    __shared__ float red[256];
    float s = 0.f;
    for (int i = threadIdx.x; i < N_TOT; i += 256) {
        float t = g_tot[i];
        float p = g_pos[i] + EPS_ * t;
        s += logf(p / t);
    }
    red[threadIdx.x] = s;
    __syncthreads();
    for (int st = 128; st; st >>= 1) {
        if (threadIdx.x < st) red[threadIdx.x] += red[threadIdx.x + st];
        __syncthreads();
    }
    if (threadIdx.x == 0) out[0] = -red[0] / (float)N_TOT;
}

// ---------------------------------------------------------------------------
extern "C" void kernel_launch(void* const* d_in, const int* in_sizes, int n_in,
                              void* d_out, int out_size) {
    const float* feats  = (const float*)d_in[0];
    const int*   labels = (const int*)d_in[1];
    float*       out    = (float*)d_out;

    prep_kernel<<<512, 256>>>(feats);

    cudaFuncSetAttribute(gemm_kernel, cudaFuncAttributeMaxDynamicSharedMemorySize, SMEM_TOTAL);
    gemm_kernel<<<148, 256, SMEM_TOTAL>>>(labels);   // all SMs, 14/15-tile ranges

    finalize_kernel<<<1, 256>>>(out);
}